// round 1
// baseline (speedup 1.0000x reference)
#include <cuda_runtime.h>
#include <cuda_bf16.h>
#include <math.h>

#define BATCH 16384
#define MAX_ACTIVE 32
#define FEAT 768
#define HIDDEN 1024
#define TH 128
#define NTILE (HIDDEN / TH)                 // 8
#define NCHUNK 18
#define RPC ((BATCH + NCHUNK - 1) / NCHUNK) // 911 rows per chunk
#define NWARP 16
#define NTHREADS (NWARP * 32)
#define SMEM_BYTES ((FEAT + 1) * TH * 2)    // 196864 B (zero row at f=FEAT)

// Scratch (no allocations allowed): transposed bf16 weights + per-tile partials
__device__ __align__(16) __nv_bfloat16 g_wt[FEAT * HIDDEN]; // wt[f][h]
__device__ float g_part[NTILE * BATCH];

// ---------------- prep: transpose ft_w (HIDDEN,FEAT) fp32 -> g_wt (FEAT,HIDDEN) bf16
__global__ void prep_kernel(const float* __restrict__ ft_w) {
    __shared__ float s[32][33];
    int f0 = blockIdx.x * 32;
    int h0 = blockIdx.y * 32;
    int tx = threadIdx.x, ty = threadIdx.y; // 32 x 8
#pragma unroll
    for (int j = 0; j < 4; j++)
        s[ty + 8 * j][tx] = ft_w[(h0 + ty + 8 * j) * FEAT + f0 + tx]; // s[h_local][f_local]
    __syncthreads();
#pragma unroll
    for (int j = 0; j < 4; j++) {
        int fl = ty + 8 * j;
        g_wt[(f0 + fl) * HIDDEN + (h0 + tx)] = __float2bfloat16(s[tx][fl]);
    }
}

// ---------------- packed fp32x2 helpers (Blackwell add.rn.f32x2)
__device__ __forceinline__ unsigned long long pk2(float x, float y) {
    unsigned long long r;
    asm("mov.b64 %0, {%1, %2};" : "=l"(r) : "f"(x), "f"(y));
    return r;
}
__device__ __forceinline__ float2 unpk2(unsigned long long a) {
    float2 r;
    asm("mov.b64 {%0, %1}, %2;" : "=f"(r.x), "=f"(r.y) : "l"(a));
    return r;
}
// a(.x,.y) += (bf16_lo(w), bf16_hi(w))  -- bf16->f32 is a pure bit shift/mask (ALU pipe)
__device__ __forceinline__ void acc_bf2(unsigned w, unsigned long long& a) {
    asm("{\n\t"
        ".reg .b32 lo, hi;\n\t"
        ".reg .b64 v;\n\t"
        "shl.b32 lo, %1, 16;\n\t"
        "and.b32 hi, %1, 0xffff0000;\n\t"
        "mov.b64 v, {lo, hi};\n\t"
        "add.rn.f32x2 %0, %0, v;\n\t"
        "}" : "+l"(a) : "r"(w));
}

// ---------------- main gather kernel: grid (NCHUNK, NTILE), 512 threads
__global__ void __launch_bounds__(NTHREADS, 1)
gather_kernel(const int* __restrict__ stm, const int* __restrict__ nstm,
              const float* __restrict__ ft_b, const float* __restrict__ out_w) {
    extern __shared__ __align__(16) unsigned char smem_raw[];
    uint4* dtile = (uint4*)smem_raw;
    const unsigned* t32 = (const unsigned*)smem_raw;

    const int tileIdx = blockIdx.y;
    const int h0 = tileIdx * TH;

    // Cooperative tile load: (FEAT+1) rows of TH bf16 (256B each); row FEAT = zeros
    const uint4* src = (const uint4*)g_wt;
    const int U4_PER_ROW = TH / 8; // 16
    for (int i = threadIdx.x; i < FEAT * U4_PER_ROW; i += NTHREADS) {
        int f = i / U4_PER_ROW;
        int c = i - f * U4_PER_ROW;
        dtile[i] = src[f * (HIDDEN / 8) + h0 / 8 + c];
    }
    for (int i = threadIdx.x; i < U4_PER_ROW; i += NTHREADS)
        dtile[FEAT * U4_PER_ROW + i] = make_uint4(0, 0, 0, 0);
    __syncthreads();

    const int lane = threadIdx.x & 31;
    const int warp = threadIdx.x >> 5;
    const int hl = h0 + lane * 4; // 4 hidden dims per lane

    const float fb0 = ft_b[hl + 0], fb1 = ft_b[hl + 1];
    const float fb2 = ft_b[hl + 2], fb3 = ft_b[hl + 3];
    const float owS0 = out_w[hl + 0], owS1 = out_w[hl + 1];
    const float owS2 = out_w[hl + 2], owS3 = out_w[hl + 3];
    const float owN0 = out_w[HIDDEN + hl + 0], owN1 = out_w[HIDDEN + hl + 1];
    const float owN2 = out_w[HIDDEN + hl + 2], owN3 = out_w[HIDDEN + hl + 3];

    const int row0 = blockIdx.x * RPC;
    const int row1 = min(row0 + RPC, BATCH);

    for (int r = row0 + warp; r < row1; r += NWARP) {
        int si = stm[r * MAX_ACTIVE + lane];
        int ni = nstm[r * MAX_ACTIVE + lane];
        // set-semantics dedup: keep only the lowest lane holding each value;
        // invalid/duplicate lanes -> zero row (FEAT), branch-free gather.
        unsigned ms = __match_any_sync(0xffffffffu, si);
        if (si < 0 || (__ffs(ms) - 1) != lane) si = FEAT;
        unsigned mn = __match_any_sync(0xffffffffu, ni);
        if (ni < 0 || (__ffs(mn) - 1) != lane) ni = FEAT;

        unsigned long long s01 = pk2(fb0, fb1), s23 = pk2(fb2, fb3);
        unsigned long long n01 = pk2(fb0, fb1), n23 = pk2(fb2, fb3);

#pragma unroll
        for (int j = 0; j < 32; j++) {
            int f = __shfl_sync(0xffffffffu, si, j);
            uint2 w = *(const uint2*)(t32 + f * (TH / 2) + lane * 2);
            acc_bf2(w.x, s01);
            acc_bf2(w.y, s23);
        }
#pragma unroll
        for (int j = 0; j < 32; j++) {
            int f = __shfl_sync(0xffffffffu, ni, j);
            uint2 w = *(const uint2*)(t32 + f * (TH / 2) + lane * 2);
            acc_bf2(w.x, n01);
            acc_bf2(w.y, n23);
        }

        float2 sa = unpk2(s01), sb = unpk2(s23);
        float2 na = unpk2(n01), nb = unpk2(n23);
        float p = __saturatef(sa.x) * owS0 + __saturatef(sa.y) * owS1
                + __saturatef(sb.x) * owS2 + __saturatef(sb.y) * owS3
                + __saturatef(na.x) * owN0 + __saturatef(na.y) * owN1
                + __saturatef(nb.x) * owN2 + __saturatef(nb.y) * owN3;
#pragma unroll
        for (int off = 16; off > 0; off >>= 1)
            p += __shfl_xor_sync(0xffffffffu, p, off);
        if (lane == 0) g_part[tileIdx * BATCH + r] = p;
    }
}

// ---------------- finish: sum tile partials + out_b, sigmoid
__global__ void finish_kernel(const float* __restrict__ out_b, float* __restrict__ out) {
    int i = blockIdx.x * blockDim.x + threadIdx.x;
    if (i < BATCH) {
        float z = out_b[0];
#pragma unroll
        for (int t = 0; t < NTILE; t++) z += g_part[t * BATCH + i];
        out[i] = 1.0f / (1.0f + expf(-z));
    }
}

extern "C" void kernel_launch(void* const* d_in, const int* in_sizes, int n_in,
                              void* d_out, int out_size) {
    const int* stm = (const int*)d_in[0];
    const int* nstm = (const int*)d_in[1];
    const float* ft_w = (const float*)d_in[2];
    const float* ft_b = (const float*)d_in[3];
    const float* out_w = (const float*)d_in[4];
    const float* out_b = (const float*)d_in[5];
    float* out = (float*)d_out;

    cudaFuncSetAttribute(gather_kernel, cudaFuncAttributeMaxDynamicSharedMemorySize,
                         SMEM_BYTES);

    prep_kernel<<<dim3(FEAT / 32, HIDDEN / 32), dim3(32, 8)>>>(ft_w);
    gather_kernel<<<dim3(NCHUNK, NTILE), NTHREADS, SMEM_BYTES>>>(stm, nstm, ft_b, out_w);
    finish_kernel<<<(BATCH + 255) / 256, 256>>>(out_b, out);
}

// round 3
// speedup vs baseline: 1.1311x; 1.1311x over previous
#include <cuda_runtime.h>
#include <cuda_bf16.h>
#include <math.h>

#define BATCH 16384
#define MAX_ACTIVE 32
#define FEAT 768
#define HIDDEN 1024
#define TH 128
#define NTILE (HIDDEN / TH)                 // 8
#define NCHUNK 18
#define RPC ((BATCH + NCHUNK - 1) / NCHUNK) // 911 rows per chunk
#define NWARP 16
#define NTHREADS (NWARP * 32)

// smem layout (bytes): tile (769 rows x 256B), then fb/ows/own (128 floats each)
#define TILE_BYTES ((FEAT + 1) * TH * 2)    // 196864
#define SM_FB TILE_BYTES
#define SM_OWS (SM_FB + 512)
#define SM_OWN (SM_OWS + 512)
#define SMEM_BYTES (SM_OWN + 512)           // 198400

__device__ __align__(16) __nv_bfloat16 g_wt[FEAT * HIDDEN]; // wt[f][h]
__device__ float g_part[NTILE * BATCH];

// ---------------- prep: transpose ft_w (HIDDEN,FEAT) fp32 -> g_wt (FEAT,HIDDEN) bf16
__global__ void prep_kernel(const float* __restrict__ ft_w) {
    __shared__ float s[32][33];
    int f0 = blockIdx.x * 32;
    int h0 = blockIdx.y * 32;
    int tx = threadIdx.x, ty = threadIdx.y; // 32 x 8
#pragma unroll
    for (int j = 0; j < 4; j++)
        s[ty + 8 * j][tx] = ft_w[(h0 + ty + 8 * j) * FEAT + f0 + tx];
    __syncthreads();
#pragma unroll
    for (int j = 0; j < 4; j++) {
        int fl = ty + 8 * j;
        g_wt[(f0 + fl) * HIDDEN + (h0 + tx)] = __float2bfloat16(s[tx][fl]);
    }
}

// bf16 pair (packed in u32) accumulated exactly into an f32x2 accumulator
__device__ __forceinline__ void acc_bf2(unsigned w, unsigned long long& a) {
    asm("{\n\t"
        ".reg .b32 lo, hi;\n\t"
        ".reg .b64 v;\n\t"
        "shl.b32 lo, %1, 16;\n\t"
        "and.b32 hi, %1, 0xffff0000;\n\t"
        "mov.b64 v, {lo, hi};\n\t"
        "add.rn.f32x2 %0, %0, v;\n\t"
        "}" : "+l"(a) : "r"(w));
}
__device__ __forceinline__ float2 unpk2(unsigned long long a) {
    float2 r;
    asm("mov.b64 {%0, %1}, %2;" : "=f"(r.x), "=f"(r.y) : "l"(a));
    return r;
}
// set-semantics dedup within a row held across 32 lanes; invalid/dupe -> FEAT (zero row)
__device__ __forceinline__ int dedup(int v, int lane) {
    unsigned m = __match_any_sync(0xffffffffu, v);
    return (v < 0 || (__ffs(m) - 1) != lane) ? FEAT : v;
}

// ---------------- main gather: 2 rows per warp, 8 h per lane (LDS.128)
__global__ void __launch_bounds__(NTHREADS, 1)
gather_kernel(const int* __restrict__ stm, const int* __restrict__ nstm,
              const float* __restrict__ ft_b, const float* __restrict__ out_w) {
    extern __shared__ __align__(16) unsigned char smem[];

    const int tileIdx = blockIdx.y;
    const int h0 = tileIdx * TH;

    // cooperative tile load: rows 0..767 from g_wt, row 768 = zeros
    {
        uint4* dtile = (uint4*)smem;
        const uint4* src = (const uint4*)g_wt;
        const int U4 = TH / 8; // 16 uint4 per row
        for (int i = threadIdx.x; i < FEAT * U4; i += NTHREADS) {
            int f = i / U4;
            int c = i - f * U4;
            dtile[i] = src[f * (HIDDEN / 8) + h0 / 8 + c];
        }
        for (int i = threadIdx.x; i < U4; i += NTHREADS)
            dtile[FEAT * U4 + i] = make_uint4(0, 0, 0, 0);
        float* sfb = (float*)(smem + SM_FB);
        float* sws = (float*)(smem + SM_OWS);
        float* swn = (float*)(smem + SM_OWN);
        if (threadIdx.x < TH) {
            sfb[threadIdx.x] = ft_b[h0 + threadIdx.x];
            sws[threadIdx.x] = out_w[h0 + threadIdx.x];
            swn[threadIdx.x] = out_w[HIDDEN + h0 + threadIdx.x];
        }
    }
    __syncthreads();

    const int lane = threadIdx.x & 31;
    const int warp = threadIdx.x >> 5;
    const int l16 = lane & 15;
    const bool hi_half = lane >= 16;

    const int row0 = blockIdx.x * RPC;
    const int row1 = min(row0 + RPC, BATCH);
    const int npairs = (row1 - row0 + 1) >> 1;

    const unsigned char* tbase = smem + l16 * 16; // + f*256 at use
    const float4* sfb = (const float4*)(smem + SM_FB) + l16 * 2;
    const float4* sws = (const float4*)(smem + SM_OWS) + l16 * 2;
    const float4* swn = (const float4*)(smem + SM_OWN) + l16 * 2;

    for (int p = warp; p < npairs; p += NWARP) {
        const int r0 = row0 + 2 * p;
        const int r1 = r0 + 1;
        const bool has1 = (r1 < row1);
        const int r1c = has1 ? r1 : r0;

        // row-major index regs: D?s/D?n hold row's 32 indices across lanes
        int d0s = dedup(stm[r0 * MAX_ACTIVE + lane], lane);
        int d1s = dedup(stm[r1c * MAX_ACTIVE + lane], lane);
        int d0n = dedup(nstm[r0 * MAX_ACTIVE + lane], lane);
        int d1n = dedup(nstm[r1c * MAX_ACTIVE + lane], lane);

        // redistribute: each half-warp holds its OWN row's idx [0..15] in C0, [16..31] in C1
        int t, u;
        t = __shfl_sync(0xffffffffu, d0s, l16);      u = __shfl_sync(0xffffffffu, d1s, l16);
        const int C0s = hi_half ? u : t;
        t = __shfl_sync(0xffffffffu, d0s, 16 + l16); u = __shfl_sync(0xffffffffu, d1s, 16 + l16);
        const int C1s = hi_half ? u : t;
        t = __shfl_sync(0xffffffffu, d0n, l16);      u = __shfl_sync(0xffffffffu, d1n, l16);
        const int C0n = hi_half ? u : t;
        t = __shfl_sync(0xffffffffu, d0n, 16 + l16); u = __shfl_sync(0xffffffffu, d1n, 16 + l16);
        const int C1n = hi_half ? u : t;

        unsigned long long as0 = 0, as1 = 0, as2 = 0, as3 = 0;
        unsigned long long an0 = 0, an1 = 0, an2 = 0, an3 = 0;

#pragma unroll
        for (int j = 0; j < 32; j++) {
            int f = __shfl_sync(0xffffffffu, (j < 16) ? C0s : C1s, j & 15, 16);
            uint4 w = *(const uint4*)(tbase + f * (TH * 2));
            acc_bf2(w.x, as0); acc_bf2(w.y, as1);
            acc_bf2(w.z, as2); acc_bf2(w.w, as3);
        }
#pragma unroll
        for (int j = 0; j < 32; j++) {
            int f = __shfl_sync(0xffffffffu, (j < 16) ? C0n : C1n, j & 15, 16);
            uint4 w = *(const uint4*)(tbase + f * (TH * 2));
            acc_bf2(w.x, an0); acc_bf2(w.y, an1);
            acc_bf2(w.z, an2); acc_bf2(w.w, an3);
        }

        // epilogue: bias + clamp + dot with out_w (stm half uses ows, nstm half own)
        float4 fb0 = sfb[0], fb1 = sfb[1];
        float4 ws0 = sws[0], ws1 = sws[1];
        float4 wn0 = swn[0], wn1 = swn[1];
        float2 v;
        float acc;
        v = unpk2(as0); acc  = __saturatef(v.x + fb0.x) * ws0.x + __saturatef(v.y + fb0.y) * ws0.y;
        v = unpk2(as1); acc += __saturatef(v.x + fb0.z) * ws0.z + __saturatef(v.y + fb0.w) * ws0.w;
        v = unpk2(as2); acc += __saturatef(v.x + fb1.x) * ws1.x + __saturatef(v.y + fb1.y) * ws1.y;
        v = unpk2(as3); acc += __saturatef(v.x + fb1.z) * ws1.z + __saturatef(v.y + fb1.w) * ws1.w;
        v = unpk2(an0); acc += __saturatef(v.x + fb0.x) * wn0.x + __saturatef(v.y + fb0.y) * wn0.y;
        v = unpk2(an1); acc += __saturatef(v.x + fb0.z) * wn0.z + __saturatef(v.y + fb0.w) * wn0.w;
        v = unpk2(an2); acc += __saturatef(v.x + fb1.x) * wn1.x + __saturatef(v.y + fb1.y) * wn1.y;
        v = unpk2(an3); acc += __saturatef(v.x + fb1.z) * wn1.z + __saturatef(v.y + fb1.w) * wn1.w;

#pragma unroll
        for (int off = 8; off > 0; off >>= 1)
            acc += __shfl_xor_sync(0xffffffffu, acc, off);

        if (lane == 0) g_part[tileIdx * BATCH + r0] = acc;
        if (lane == 16 && has1) g_part[tileIdx * BATCH + r1] = acc;
    }
}

// ---------------- finish: sum tile partials + out_b, sigmoid
__global__ void finish_kernel(const float* __restrict__ out_b, float* __restrict__ out) {
    int i = blockIdx.x * blockDim.x + threadIdx.x;
    if (i < BATCH) {
        float z = out_b[0];
#pragma unroll
        for (int t = 0; t < NTILE; t++) z += g_part[t * BATCH + i];
        out[i] = 1.0f / (1.0f + expf(-z));
    }
}

extern "C" void kernel_launch(void* const* d_in, const int* in_sizes, int n_in,
                              void* d_out, int out_size) {
    const int* stm = (const int*)d_in[0];
    const int* nstm = (const int*)d_in[1];
    const float* ft_w = (const float*)d_in[2];
    const float* ft_b = (const float*)d_in[3];
    const float* out_w = (const float*)d_in[4];
    const float* out_b = (const float*)d_in[5];
    float* out = (float*)d_out;

    cudaFuncSetAttribute(gather_kernel, cudaFuncAttributeMaxDynamicSharedMemorySize,
                         SMEM_BYTES);

    prep_kernel<<<dim3(FEAT / 32, HIDDEN / 32), dim3(32, 8)>>>(ft_w);
    gather_kernel<<<dim3(NCHUNK, NTILE), NTHREADS, SMEM_BYTES>>>(stm, nstm, ft_b, out_w);
    finish_kernel<<<(BATCH + 255) / 256, 256>>>(out_b, out);
}

// round 4
// speedup vs baseline: 1.2128x; 1.0722x over previous
#include <cuda_runtime.h>
#include <cuda_bf16.h>
#include <math.h>

#define BATCH 16384
#define MAX_ACTIVE 32
#define FEAT 768
#define HIDDEN 1024
#define TH 128
#define NTILE (HIDDEN / TH)                 // 8
#define NCHUNK 18
#define RPC ((BATCH + NCHUNK - 1) / NCHUNK) // 911 rows per chunk
#define NWARP 32
#define NTHREADS (NWARP * 32)               // 1024

// smem layout (bytes): tile (769 rows x 256B), then fb/ows/own (128 floats each)
#define TILE_BYTES ((FEAT + 1) * TH * 2)    // 196864
#define SM_FB TILE_BYTES
#define SM_OWS (SM_FB + 512)
#define SM_OWN (SM_OWS + 512)
#define SMEM_BYTES (SM_OWN + 512)           // 198400

__device__ __align__(16) __nv_bfloat16 g_wt[FEAT * HIDDEN]; // wt[f][h]
__device__ float g_part[NTILE * BATCH];

// ---------------- prep: transpose ft_w (HIDDEN,FEAT) fp32 -> g_wt (FEAT,HIDDEN) bf16
__global__ void prep_kernel(const float* __restrict__ ft_w) {
    __shared__ float s[32][33];
    int f0 = blockIdx.x * 32;
    int h0 = blockIdx.y * 32;
    int tx = threadIdx.x, ty = threadIdx.y; // 32 x 8
#pragma unroll
    for (int j = 0; j < 4; j++)
        s[ty + 8 * j][tx] = ft_w[(h0 + ty + 8 * j) * FEAT + f0 + tx];
    __syncthreads();
#pragma unroll
    for (int j = 0; j < 4; j++) {
        int fl = ty + 8 * j;
        g_wt[(f0 + fl) * HIDDEN + (h0 + tx)] = __float2bfloat16(s[tx][fl]);
    }
}

// bf16 pair (packed in u32) accumulated exactly into an f32x2 accumulator
__device__ __forceinline__ void acc_bf2(unsigned w, unsigned long long& a) {
    asm("{\n\t"
        ".reg .b32 lo, hi;\n\t"
        ".reg .b64 v;\n\t"
        "shl.b32 lo, %1, 16;\n\t"
        "and.b32 hi, %1, 0xffff0000;\n\t"
        "mov.b64 v, {lo, hi};\n\t"
        "add.rn.f32x2 %0, %0, v;\n\t"
        "}" : "+l"(a) : "r"(w));
}
__device__ __forceinline__ float2 unpk2(unsigned long long a) {
    float2 r;
    asm("mov.b64 {%0, %1}, %2;" : "=f"(r.x), "=f"(r.y) : "l"(a));
    return r;
}
// set-semantics dedup within a row held across 32 lanes; invalid/dupe -> FEAT (zero row)
__device__ __forceinline__ int dedup(int v, int lane) {
    unsigned m = __match_any_sync(0xffffffffu, v);
    return (v < 0 || (__ffs(m) - 1) != lane) ? FEAT : v;
}

// ---------------- main gather: 2 rows per warp, 8 h per lane (LDS.128), packed idx bcast
__global__ void __launch_bounds__(NTHREADS, 1)
gather_kernel(const int* __restrict__ stm, const int* __restrict__ nstm,
              const float* __restrict__ ft_b, const float* __restrict__ out_w) {
    extern __shared__ __align__(16) unsigned char smem[];

    const int tileIdx = blockIdx.y;
    const int h0 = tileIdx * TH;

    // cooperative tile load: rows 0..767 from g_wt, row 768 = zeros
    {
        uint4* dtile = (uint4*)smem;
        const uint4* src = (const uint4*)g_wt;
        const int U4 = TH / 8; // 16 uint4 per row
        for (int i = threadIdx.x; i < FEAT * U4; i += NTHREADS) {
            int f = i / U4;
            int c = i - f * U4;
            dtile[i] = src[f * (HIDDEN / 8) + h0 / 8 + c];
        }
        if (threadIdx.x < U4) dtile[FEAT * U4 + threadIdx.x] = make_uint4(0, 0, 0, 0);
        float* sfb = (float*)(smem + SM_FB);
        float* sws = (float*)(smem + SM_OWS);
        float* swn = (float*)(smem + SM_OWN);
        if (threadIdx.x >= NTHREADS - TH) {
            int t = threadIdx.x - (NTHREADS - TH);
            sfb[t] = ft_b[h0 + t];
            sws[t] = out_w[h0 + t];
            swn[t] = out_w[HIDDEN + h0 + t];
        }
    }
    __syncthreads();

    const int lane = threadIdx.x & 31;
    const int warp = threadIdx.x >> 5;
    const int l16 = lane & 15;
    const bool hi_half = lane >= 16;

    const int row0 = blockIdx.x * RPC;
    const int row1 = min(row0 + RPC, BATCH);
    const int npairs = (row1 - row0 + 1) >> 1;

    const unsigned char* tbase = smem + l16 * 16; // + f*256 at use
    const float4* sfb = (const float4*)(smem + SM_FB) + l16 * 2;
    const float4* sws = (const float4*)(smem + SM_OWS) + l16 * 2;
    const float4* swn = (const float4*)(smem + SM_OWN) + l16 * 2;

    for (int p = warp; p < npairs; p += NWARP) {
        const int r0 = row0 + 2 * p;
        const int r1 = r0 + 1;
        const bool has1 = (r1 < row1);
        const int r1c = has1 ? r1 : r0;

        // row-major index regs: each holds a row's 32 indices across lanes
        int d0s = dedup(stm[r0 * MAX_ACTIVE + lane], lane);
        int d1s = dedup(stm[r1c * MAX_ACTIVE + lane], lane);
        int d0n = dedup(nstm[r0 * MAX_ACTIVE + lane], lane);
        int d1n = dedup(nstm[r1c * MAX_ACTIVE + lane], lane);

        // redistribute + pack: lane l16 of each half holds its own row's
        // features (2*l16, 2*l16+1) packed 16-bit (idx in [0,768] fits)
        int a, b, pk0, pk1;
        a = __shfl_sync(0xffffffffu, d0s, 2 * l16);
        b = __shfl_sync(0xffffffffu, d0s, 2 * l16 + 1);
        pk0 = a | (b << 16);
        a = __shfl_sync(0xffffffffu, d1s, 2 * l16);
        b = __shfl_sync(0xffffffffu, d1s, 2 * l16 + 1);
        pk1 = a | (b << 16);
        const int Ps = hi_half ? pk1 : pk0;
        a = __shfl_sync(0xffffffffu, d0n, 2 * l16);
        b = __shfl_sync(0xffffffffu, d0n, 2 * l16 + 1);
        pk0 = a | (b << 16);
        a = __shfl_sync(0xffffffffu, d1n, 2 * l16);
        b = __shfl_sync(0xffffffffu, d1n, 2 * l16 + 1);
        pk1 = a | (b << 16);
        const int Pn = hi_half ? pk1 : pk0;

        unsigned long long as0 = 0, as1 = 0, as2 = 0, as3 = 0;
        unsigned long long an0 = 0, an1 = 0, an2 = 0, an3 = 0;

#pragma unroll
        for (int j = 0; j < 16; j++) {
            int pk = __shfl_sync(0xffffffffu, Ps, j, 16);
            int f0 = pk & 0xffff;
            int f1 = ((unsigned)pk) >> 16;
            uint4 w = *(const uint4*)(tbase + f0 * (TH * 2));
            acc_bf2(w.x, as0); acc_bf2(w.y, as1);
            acc_bf2(w.z, as2); acc_bf2(w.w, as3);
            uint4 w2 = *(const uint4*)(tbase + f1 * (TH * 2));
            acc_bf2(w2.x, as0); acc_bf2(w2.y, as1);
            acc_bf2(w2.z, as2); acc_bf2(w2.w, as3);
        }
#pragma unroll
        for (int j = 0; j < 16; j++) {
            int pk = __shfl_sync(0xffffffffu, Pn, j, 16);
            int f0 = pk & 0xffff;
            int f1 = ((unsigned)pk) >> 16;
            uint4 w = *(const uint4*)(tbase + f0 * (TH * 2));
            acc_bf2(w.x, an0); acc_bf2(w.y, an1);
            acc_bf2(w.z, an2); acc_bf2(w.w, an3);
            uint4 w2 = *(const uint4*)(tbase + f1 * (TH * 2));
            acc_bf2(w2.x, an0); acc_bf2(w2.y, an1);
            acc_bf2(w2.z, an2); acc_bf2(w2.w, an3);
        }

        // epilogue: bias + clamp + dot with out_w (stm half uses ows, nstm half own)
        float4 fb0 = sfb[0], fb1 = sfb[1];
        float4 ws0 = sws[0], ws1 = sws[1];
        float4 wn0 = swn[0], wn1 = swn[1];
        float2 v;
        float acc;
        v = unpk2(as0); acc  = __saturatef(v.x + fb0.x) * ws0.x + __saturatef(v.y + fb0.y) * ws0.y;
        v = unpk2(as1); acc += __saturatef(v.x + fb0.z) * ws0.z + __saturatef(v.y + fb0.w) * ws0.w;
        v = unpk2(as2); acc += __saturatef(v.x + fb1.x) * ws1.x + __saturatef(v.y + fb1.y) * ws1.y;
        v = unpk2(as3); acc += __saturatef(v.x + fb1.z) * ws1.z + __saturatef(v.y + fb1.w) * ws1.w;
        v = unpk2(an0); acc += __saturatef(v.x + fb0.x) * wn0.x + __saturatef(v.y + fb0.y) * wn0.y;
        v = unpk2(an1); acc += __saturatef(v.x + fb0.z) * wn0.z + __saturatef(v.y + fb0.w) * wn0.w;
        v = unpk2(an2); acc += __saturatef(v.x + fb1.x) * wn1.x + __saturatef(v.y + fb1.y) * wn1.y;
        v = unpk2(an3); acc += __saturatef(v.x + fb1.z) * wn1.z + __saturatef(v.y + fb1.w) * wn1.w;

#pragma unroll
        for (int off = 8; off > 0; off >>= 1)
            acc += __shfl_xor_sync(0xffffffffu, acc, off);

        if (lane == 0) g_part[tileIdx * BATCH + r0] = acc;
        if (lane == 16 && has1) g_part[tileIdx * BATCH + r1] = acc;
    }
}

// ---------------- finish: sum tile partials + out_b, sigmoid
__global__ void finish_kernel(const float* __restrict__ out_b, float* __restrict__ out) {
    int i = blockIdx.x * blockDim.x + threadIdx.x;
    if (i < BATCH) {
        float z = out_b[0];
#pragma unroll
        for (int t = 0; t < NTILE; t++) z += g_part[t * BATCH + i];
        out[i] = 1.0f / (1.0f + expf(-z));
    }
}

extern "C" void kernel_launch(void* const* d_in, const int* in_sizes, int n_in,
                              void* d_out, int out_size) {
    const int* stm = (const int*)d_in[0];
    const int* nstm = (const int*)d_in[1];
    const float* ft_w = (const float*)d_in[2];
    const float* ft_b = (const float*)d_in[3];
    const float* out_w = (const float*)d_in[4];
    const float* out_b = (const float*)d_in[5];
    float* out = (float*)d_out;

    cudaFuncSetAttribute(gather_kernel, cudaFuncAttributeMaxDynamicSharedMemorySize,
                         SMEM_BYTES);

    prep_kernel<<<dim3(FEAT / 32, HIDDEN / 32), dim3(32, 8)>>>(ft_w);
    gather_kernel<<<dim3(NCHUNK, NTILE), NTHREADS, SMEM_BYTES>>>(stm, nstm, ft_b, out_w);
    finish_kernel<<<(BATCH + 255) / 256, 256>>>(out_b, out);
}

// round 5
// speedup vs baseline: 1.2232x; 1.0085x over previous
#include <cuda_runtime.h>
#include <cuda_bf16.h>
#include <math.h>

#define BATCH 16384
#define MAX_ACTIVE 32
#define FEAT 768
#define HIDDEN 1024
#define TH 128
#define NTILE (HIDDEN / TH)                 // 8
#define NCHUNK 18
#define RPC ((BATCH + NCHUNK - 1) / NCHUNK) // 911 rows per chunk
#define NWARP 32
#define NTHREADS (NWARP * 32)               // 1024

#define TILE_BYTES ((FEAT + 1) * TH * 2)    // 196864
#define SM_FB TILE_BYTES
#define SM_OWS (SM_FB + 512)
#define SM_OWN (SM_OWS + 512)
#define SMEM_BYTES (SM_OWN + 512)           // 198400

__device__ __align__(16) __nv_bfloat16 g_wt[FEAT * HIDDEN]; // wt[f][h]
__device__ float g_part[NTILE * BATCH];

// ---------------- prep: transpose ft_w (HIDDEN,FEAT) fp32 -> g_wt (FEAT,HIDDEN) bf16
__global__ void prep_kernel(const float* __restrict__ ft_w) {
    __shared__ float s[32][33];
    int f0 = blockIdx.x * 32;
    int h0 = blockIdx.y * 32;
    int tx = threadIdx.x, ty = threadIdx.y; // 32 x 8
#pragma unroll
    for (int j = 0; j < 4; j++)
        s[ty + 8 * j][tx] = ft_w[(h0 + ty + 8 * j) * FEAT + f0 + tx];
    __syncthreads();
#pragma unroll
    for (int j = 0; j < 4; j++) {
        int fl = ty + 8 * j;
        g_wt[(f0 + fl) * HIDDEN + (h0 + tx)] = __float2bfloat16(s[tx][fl]);
    }
}

// pairwise bf16x2 add (FMA pipe, 1 instr for 2 lanes)
__device__ __forceinline__ unsigned hadd2bf(unsigned a, unsigned b) {
    unsigned r;
    asm("add.rn.bf16x2 %0, %1, %2;" : "=r"(r) : "r"(a), "r"(b));
    return r;
}
// bf16 pair (packed u32) accumulated exactly into an f32x2 accumulator
__device__ __forceinline__ void acc_bf2(unsigned w, unsigned long long& a) {
    asm("{\n\t"
        ".reg .b32 lo, hi;\n\t"
        ".reg .b64 v;\n\t"
        "shl.b32 lo, %1, 16;\n\t"
        "and.b32 hi, %1, 0xffff0000;\n\t"
        "mov.b64 v, {lo, hi};\n\t"
        "add.rn.f32x2 %0, %0, v;\n\t"
        "}" : "+l"(a) : "r"(w));
}
__device__ __forceinline__ float2 unpk2(unsigned long long a) {
    float2 r;
    asm("mov.b64 {%0, %1}, %2;" : "=f"(r.x), "=f"(r.y) : "l"(a));
    return r;
}
// set-semantics dedup within a row held across 32 lanes; invalid/dupe -> FEAT (zero row)
__device__ __forceinline__ int dedup(int v, int lane) {
    unsigned m = __match_any_sync(0xffffffffu, v);
    return (v < 0 || (__ffs(m) - 1) != lane) ? FEAT : v;
}

// ---------------- main gather: 2 rows per warp, 8 h per lane, bf16 pair pre-add
__global__ void __launch_bounds__(NTHREADS, 1)
gather_kernel(const int* __restrict__ stm, const int* __restrict__ nstm,
              const float* __restrict__ ft_b, const float* __restrict__ out_w) {
    extern __shared__ __align__(16) unsigned char smem[];

    const int tileIdx = blockIdx.y;
    const int h0 = tileIdx * TH;

    {
        uint4* dtile = (uint4*)smem;
        const uint4* src = (const uint4*)g_wt;
        const int U4 = TH / 8; // 16 uint4 per row
        for (int i = threadIdx.x; i < FEAT * U4; i += NTHREADS) {
            int f = i / U4;
            int c = i - f * U4;
            dtile[i] = src[f * (HIDDEN / 8) + h0 / 8 + c];
        }
        if (threadIdx.x < U4) dtile[FEAT * U4 + threadIdx.x] = make_uint4(0, 0, 0, 0);
        float* sfb = (float*)(smem + SM_FB);
        float* sws = (float*)(smem + SM_OWS);
        float* swn = (float*)(smem + SM_OWN);
        if (threadIdx.x >= NTHREADS - TH) {
            int t = threadIdx.x - (NTHREADS - TH);
            sfb[t] = ft_b[h0 + t];
            sws[t] = out_w[h0 + t];
            swn[t] = out_w[HIDDEN + h0 + t];
        }
    }
    __syncthreads();

    const int lane = threadIdx.x & 31;
    const int warp = threadIdx.x >> 5;
    const int l16 = lane & 15;
    const bool hi_half = lane >= 16;

    const int row0 = blockIdx.x * RPC;
    const int row1 = min(row0 + RPC, BATCH);
    const int npairs = (row1 - row0 + 1) >> 1;

    const unsigned char* tbase = smem + l16 * 16;
    const float4* sfb = (const float4*)(smem + SM_FB) + l16 * 2;
    const float4* sws = (const float4*)(smem + SM_OWS) + l16 * 2;
    const float4* swn = (const float4*)(smem + SM_OWN) + l16 * 2;

    for (int p = warp; p < npairs; p += NWARP) {
        const int r0 = row0 + 2 * p;
        const int r1 = r0 + 1;
        const bool has1 = (r1 < row1);
        const int r1c = has1 ? r1 : r0;

        int d0s = dedup(stm[r0 * MAX_ACTIVE + lane], lane);
        int d1s = dedup(stm[r1c * MAX_ACTIVE + lane], lane);
        int d0n = dedup(nstm[r0 * MAX_ACTIVE + lane], lane);
        int d1n = dedup(nstm[r1c * MAX_ACTIVE + lane], lane);

        // redistribute + pack: lane l16 of each half holds its own row's
        // features (2*l16, 2*l16+1) packed 16-bit
        int a, b, pk0, pk1;
        a = __shfl_sync(0xffffffffu, d0s, 2 * l16);
        b = __shfl_sync(0xffffffffu, d0s, 2 * l16 + 1);
        pk0 = a | (b << 16);
        a = __shfl_sync(0xffffffffu, d1s, 2 * l16);
        b = __shfl_sync(0xffffffffu, d1s, 2 * l16 + 1);
        pk1 = a | (b << 16);
        const int Ps = hi_half ? pk1 : pk0;
        a = __shfl_sync(0xffffffffu, d0n, 2 * l16);
        b = __shfl_sync(0xffffffffu, d0n, 2 * l16 + 1);
        pk0 = a | (b << 16);
        a = __shfl_sync(0xffffffffu, d1n, 2 * l16);
        b = __shfl_sync(0xffffffffu, d1n, 2 * l16 + 1);
        pk1 = a | (b << 16);
        const int Pn = hi_half ? pk1 : pk0;

        unsigned long long as0 = 0, as1 = 0, as2 = 0, as3 = 0;
        unsigned long long an0 = 0, an1 = 0, an2 = 0, an3 = 0;

#pragma unroll
        for (int j = 0; j < 16; j++) {
            int pk = __shfl_sync(0xffffffffu, Ps, j, 16);
            int f0 = pk & 0xffff;
            int f1 = ((unsigned)pk) >> 16;
            uint4 w = *(const uint4*)(tbase + f0 * (TH * 2));
            uint4 w2 = *(const uint4*)(tbase + f1 * (TH * 2));
            acc_bf2(hadd2bf(w.x, w2.x), as0);
            acc_bf2(hadd2bf(w.y, w2.y), as1);
            acc_bf2(hadd2bf(w.z, w2.z), as2);
            acc_bf2(hadd2bf(w.w, w2.w), as3);
        }
#pragma unroll
        for (int j = 0; j < 16; j++) {
            int pk = __shfl_sync(0xffffffffu, Pn, j, 16);
            int f0 = pk & 0xffff;
            int f1 = ((unsigned)pk) >> 16;
            uint4 w = *(const uint4*)(tbase + f0 * (TH * 2));
            uint4 w2 = *(const uint4*)(tbase + f1 * (TH * 2));
            acc_bf2(hadd2bf(w.x, w2.x), an0);
            acc_bf2(hadd2bf(w.y, w2.y), an1);
            acc_bf2(hadd2bf(w.z, w2.z), an2);
            acc_bf2(hadd2bf(w.w, w2.w), an3);
        }

        float4 fb0 = sfb[0], fb1 = sfb[1];
        float4 ws0 = sws[0], ws1 = sws[1];
        float4 wn0 = swn[0], wn1 = swn[1];
        float2 v;
        float acc;
        v = unpk2(as0); acc  = __saturatef(v.x + fb0.x) * ws0.x + __saturatef(v.y + fb0.y) * ws0.y;
        v = unpk2(as1); acc += __saturatef(v.x + fb0.z) * ws0.z + __saturatef(v.y + fb0.w) * ws0.w;
        v = unpk2(as2); acc += __saturatef(v.x + fb1.x) * ws1.x + __saturatef(v.y + fb1.y) * ws1.y;
        v = unpk2(as3); acc += __saturatef(v.x + fb1.z) * ws1.z + __saturatef(v.y + fb1.w) * ws1.w;
        v = unpk2(an0); acc += __saturatef(v.x + fb0.x) * wn0.x + __saturatef(v.y + fb0.y) * wn0.y;
        v = unpk2(an1); acc += __saturatef(v.x + fb0.z) * wn0.z + __saturatef(v.y + fb0.w) * wn0.w;
        v = unpk2(an2); acc += __saturatef(v.x + fb1.x) * wn1.x + __saturatef(v.y + fb1.y) * wn1.y;
        v = unpk2(an3); acc += __saturatef(v.x + fb1.z) * wn1.z + __saturatef(v.y + fb1.w) * wn1.w;

#pragma unroll
        for (int off = 8; off > 0; off >>= 1)
            acc += __shfl_xor_sync(0xffffffffu, acc, off);

        if (lane == 0) g_part[tileIdx * BATCH + r0] = acc;
        if (lane == 16 && has1) g_part[tileIdx * BATCH + r1] = acc;
    }
}

// ---------------- finish: sum tile partials + out_b, sigmoid
__global__ void finish_kernel(const float* __restrict__ out_b, float* __restrict__ out) {
    int i = blockIdx.x * blockDim.x + threadIdx.x;
    if (i < BATCH) {
        float z = out_b[0];
#pragma unroll
        for (int t = 0; t < NTILE; t++) z += g_part[t * BATCH + i];
        out[i] = 1.0f / (1.0f + expf(-z));
    }
}

extern "C" void kernel_launch(void* const* d_in, const int* in_sizes, int n_in,
                              void* d_out, int out_size) {
    const int* stm = (const int*)d_in[0];
    const int* nstm = (const int*)d_in[1];
    const float* ft_w = (const float*)d_in[2];
    const float* ft_b = (const float*)d_in[3];
    const float* out_w = (const float*)d_in[4];
    const float* out_b = (const float*)d_in[5];
    float* out = (float*)d_out;

    cudaFuncSetAttribute(gather_kernel, cudaFuncAttributeMaxDynamicSharedMemorySize,
                         SMEM_BYTES);

    prep_kernel<<<dim3(FEAT / 32, HIDDEN / 32), dim3(32, 8)>>>(ft_w);
    gather_kernel<<<dim3(NCHUNK, NTILE), NTHREADS, SMEM_BYTES>>>(stm, nstm, ft_b, out_w);
    finish_kernel<<<(BATCH + 255) / 256, 256>>>(out_b, out);
}

// round 6
// speedup vs baseline: 1.2259x; 1.0022x over previous
#include <cuda_runtime.h>
#include <cuda_bf16.h>
#include <math.h>

#define BATCH 16384
#define MAX_ACTIVE 32
#define FEAT 768
#define HIDDEN 1024
#define TH 128
#define NTILE (HIDDEN / TH)                 // 8
#define NCHUNK 18
#define RPC ((BATCH + NCHUNK - 1) / NCHUNK) // 911 rows per chunk
#define NWARP 32
#define NTHREADS (NWARP * 32)               // 1024

#define TILE_BYTES ((FEAT + 1) * TH * 2)    // 196864
#define SM_FB TILE_BYTES
#define SM_OWS (SM_FB + 512)
#define SM_OWN (SM_OWS + 512)
#define SM_STAGE (SM_OWN + 512)             // 32 warps x 256B staging
#define SMEM_BYTES (SM_STAGE + NWARP * 256) // 206592

__device__ __align__(16) __nv_bfloat16 g_wt[FEAT * HIDDEN]; // wt[f][h]
__device__ float g_part[NTILE * BATCH];

// ---------------- prep: transpose ft_w (HIDDEN,FEAT) fp32 -> g_wt (FEAT,HIDDEN) bf16
__global__ void prep_kernel(const float* __restrict__ ft_w) {
    __shared__ float s[32][33];
    int f0 = blockIdx.x * 32;
    int h0 = blockIdx.y * 32;
    int tx = threadIdx.x, ty = threadIdx.y; // 32 x 8
#pragma unroll
    for (int j = 0; j < 4; j++)
        s[ty + 8 * j][tx] = ft_w[(h0 + ty + 8 * j) * FEAT + f0 + tx];
    __syncthreads();
#pragma unroll
    for (int j = 0; j < 4; j++) {
        int fl = ty + 8 * j;
        g_wt[(f0 + fl) * HIDDEN + (h0 + tx)] = __float2bfloat16(s[tx][fl]);
    }
}

// pairwise bf16x2 add (FMA pipe)
__device__ __forceinline__ unsigned hadd2bf(unsigned a, unsigned b) {
    unsigned r;
    asm("add.rn.bf16x2 %0, %1, %2;" : "=r"(r) : "r"(a), "r"(b));
    return r;
}
// bf16 pair (packed u32) accumulated into f32x2 accumulator
__device__ __forceinline__ void acc_bf2(unsigned w, unsigned long long& a) {
    asm("{\n\t"
        ".reg .b32 lo, hi;\n\t"
        ".reg .b64 v;\n\t"
        "shl.b32 lo, %1, 16;\n\t"
        "and.b32 hi, %1, 0xffff0000;\n\t"
        "mov.b64 v, {lo, hi};\n\t"
        "add.rn.f32x2 %0, %0, v;\n\t"
        "}" : "+l"(a) : "r"(w));
}
__device__ __forceinline__ float2 unpk2(unsigned long long a) {
    float2 r;
    asm("mov.b64 {%0, %1}, %2;" : "=f"(r.x), "=f"(r.y) : "l"(a));
    return r;
}
// set-semantics dedup; invalid/dupe -> FEAT (zero row)
__device__ __forceinline__ int dedup(int v, int lane) {
    unsigned m = __match_any_sync(0xffffffffu, v);
    return (v < 0 || (__ffs(m) - 1) != lane) ? FEAT : v;
}

// process 8 features packed as u16 x8 in a uint4 (byte offsets = f*256)
__device__ __forceinline__ void acc8(const unsigned char* tbase, uint4 ix,
                                     unsigned long long& a0, unsigned long long& a1,
                                     unsigned long long& a2, unsigned long long& a3) {
#pragma unroll
    for (int q = 0; q < 4; q++) {
        unsigned u = (q == 0) ? ix.x : (q == 1) ? ix.y : (q == 2) ? ix.z : ix.w;
        unsigned f0 = (u & 0xffffu) << 8;   // *256
        unsigned f1 = (u >> 16) << 8;
        uint4 w = *(const uint4*)(tbase + f0);
        uint4 w2 = *(const uint4*)(tbase + f1);
        acc_bf2(hadd2bf(w.x, w2.x), a0);
        acc_bf2(hadd2bf(w.y, w2.y), a1);
        acc_bf2(hadd2bf(w.z, w2.z), a2);
        acc_bf2(hadd2bf(w.w, w2.w), a3);
    }
}

// ---------------- main gather: 2 rows/warp, 8 h/lane, smem-broadcast idx staging
__global__ void __launch_bounds__(NTHREADS, 1)
gather_kernel(const int* __restrict__ stm, const int* __restrict__ nstm,
              const float* __restrict__ ft_b, const float* __restrict__ out_w) {
    extern __shared__ __align__(16) unsigned char smem[];

    const int tileIdx = blockIdx.y;
    const int h0 = tileIdx * TH;

    {
        uint4* dtile = (uint4*)smem;
        const uint4* src = (const uint4*)g_wt;
        const int U4 = TH / 8; // 16 uint4 per row
        for (int i = threadIdx.x; i < FEAT * U4; i += NTHREADS) {
            int f = i >> 4;
            int c = i & 15;
            dtile[i] = src[f * (HIDDEN / 8) + h0 / 8 + c];
        }
        if (threadIdx.x < U4) dtile[FEAT * U4 + threadIdx.x] = make_uint4(0, 0, 0, 0);
        float* sfb = (float*)(smem + SM_FB);
        float* sws = (float*)(smem + SM_OWS);
        float* swn = (float*)(smem + SM_OWN);
        if (threadIdx.x >= NTHREADS - TH) {
            int t = threadIdx.x - (NTHREADS - TH);
            sfb[t] = ft_b[h0 + t];
            sws[t] = out_w[h0 + t];
            swn[t] = out_w[HIDDEN + h0 + t];
        }
    }
    __syncthreads();

    const int lane = threadIdx.x & 31;
    const int warp = threadIdx.x >> 5;
    const int l16 = lane & 15;
    const bool hi_half = lane >= 16;

    const int row0 = blockIdx.x * RPC;
    const int row1 = min(row0 + RPC, BATCH);
    const int npairs = (row1 - row0 + 1) >> 1;

    const unsigned char* tbase = smem + l16 * 16;
    unsigned char* stg = smem + SM_STAGE + warp * 256;
    // my half's stm idx at stg + (hi?64:0); nstm at +128
    const unsigned char* myS = stg + (hi_half ? 64 : 0);
    const unsigned char* myN = myS + 128;
    const float4* sfb = (const float4*)(smem + SM_FB) + l16 * 2;
    const float4* sws = (const float4*)(smem + SM_OWS) + l16 * 2;
    const float4* swn = (const float4*)(smem + SM_OWN) + l16 * 2;

    for (int p = warp; p < npairs; p += NWARP) {
        const int r0 = row0 + 2 * p;
        const int r1 = r0 + 1;
        const bool has1 = (r1 < row1);
        const int r1c = has1 ? r1 : r0;

        int d0s = dedup(stm[r0 * MAX_ACTIVE + lane], lane);
        int d1s = dedup(stm[r1c * MAX_ACTIVE + lane], lane);
        int d0n = dedup(nstm[r0 * MAX_ACTIVE + lane], lane);
        int d1n = dedup(nstm[r1c * MAX_ACTIVE + lane], lane);

        // stage packed u16 indices: [r0s][r1s][r0n][r1n], 64B each
        *(unsigned short*)(stg + lane * 2) = (unsigned short)d0s;
        *(unsigned short*)(stg + 64 + lane * 2) = (unsigned short)d1s;
        *(unsigned short*)(stg + 128 + lane * 2) = (unsigned short)d0n;
        *(unsigned short*)(stg + 192 + lane * 2) = (unsigned short)d1n;
        __syncwarp();

        unsigned long long as0 = 0, as1 = 0, as2 = 0, as3 = 0;
        unsigned long long an0 = 0, an1 = 0, an2 = 0, an3 = 0;

#pragma unroll
        for (int j = 0; j < 4; j++) {
            uint4 ix = *(const uint4*)(myS + j * 16); // 8 idx, broadcast load
            acc8(tbase, ix, as0, as1, as2, as3);
        }
#pragma unroll
        for (int j = 0; j < 4; j++) {
            uint4 ix = *(const uint4*)(myN + j * 16);
            acc8(tbase, ix, an0, an1, an2, an3);
        }

        float4 fb0 = sfb[0], fb1 = sfb[1];
        float4 ws0 = sws[0], ws1 = sws[1];
        float4 wn0 = swn[0], wn1 = swn[1];
        float2 v;
        float acc;
        v = unpk2(as0); acc  = __saturatef(v.x + fb0.x) * ws0.x + __saturatef(v.y + fb0.y) * ws0.y;
        v = unpk2(as1); acc += __saturatef(v.x + fb0.z) * ws0.z + __saturatef(v.y + fb0.w) * ws0.w;
        v = unpk2(as2); acc += __saturatef(v.x + fb1.x) * ws1.x + __saturatef(v.y + fb1.y) * ws1.y;
        v = unpk2(as3); acc += __saturatef(v.x + fb1.z) * ws1.z + __saturatef(v.y + fb1.w) * ws1.w;
        v = unpk2(an0); acc += __saturatef(v.x + fb0.x) * wn0.x + __saturatef(v.y + fb0.y) * wn0.y;
        v = unpk2(an1); acc += __saturatef(v.x + fb0.z) * wn0.z + __saturatef(v.y + fb0.w) * wn0.w;
        v = unpk2(an2); acc += __saturatef(v.x + fb1.x) * wn1.x + __saturatef(v.y + fb1.y) * wn1.y;
        v = unpk2(an3); acc += __saturatef(v.x + fb1.z) * wn1.z + __saturatef(v.y + fb1.w) * wn1.w;

        // reduce within each 16-lane half (also reconverges warp before next STS)
#pragma unroll
        for (int off = 8; off > 0; off >>= 1)
            acc += __shfl_xor_sync(0xffffffffu, acc, off);

        if (lane == 0) g_part[tileIdx * BATCH + r0] = acc;
        if (lane == 16 && has1) g_part[tileIdx * BATCH + r1] = acc;
    }
}

// ---------------- finish: sum tile partials + out_b, sigmoid
__global__ void finish_kernel(const float* __restrict__ out_b, float* __restrict__ out) {
    int i = blockIdx.x * blockDim.x + threadIdx.x;
    if (i < BATCH) {
        float z = out_b[0];
#pragma unroll
        for (int t = 0; t < NTILE; t++) z += g_part[t * BATCH + i];
        out[i] = 1.0f / (1.0f + expf(-z));
    }
}

extern "C" void kernel_launch(void* const* d_in, const int* in_sizes, int n_in,
                              void* d_out, int out_size) {
    const int* stm = (const int*)d_in[0];
    const int* nstm = (const int*)d_in[1];
    const float* ft_w = (const float*)d_in[2];
    const float* ft_b = (const float*)d_in[3];
    const float* out_w = (const float*)d_in[4];
    const float* out_b = (const float*)d_in[5];
    float* out = (float*)d_out;

    cudaFuncSetAttribute(gather_kernel, cudaFuncAttributeMaxDynamicSharedMemorySize,
                         SMEM_BYTES);

    prep_kernel<<<dim3(FEAT / 32, HIDDEN / 32), dim3(32, 8)>>>(ft_w);
    gather_kernel<<<dim3(NCHUNK, NTILE), NTHREADS, SMEM_BYTES>>>(stm, nstm, ft_b, out_w);
    finish_kernel<<<(BATCH + 255) / 256, 256>>>(out_b, out);
}